// round 3
// baseline (speedup 1.0000x reference)
#include <cuda_runtime.h>
#include <math.h>

#define NPTS   16384
#define NB     16
#define NSLOT  32          // 16 source + 16 target clouds
#define KKP    16
#define OUT_DEF (NB*NPTS*3)   // 786432
#define OUT_KP  (NB*KKP*3)    // 768
#define BN_EPS 1e-5f

// ----------------------------------------------------------------------------
// Device scratch (no allocations allowed)
// ----------------------------------------------------------------------------
__device__ float g_w1f[64*3];
__device__ float g_b1f[64];
__device__ float g_w2t[64*128];     // transposed + BN-folded: [k][d]
__device__ float g_b2f[128];
__device__ float g_w3t[128*128];    // transposed + BN-folded: [k][d]
__device__ float g_b3f[128];
__device__ int   g_lat[NSLOT*128];  // latent max (float bits; relu => >=0)
__device__ float g_kp[NSLOT*48];    // MLP-predicted keypoints
__device__ float g_sel[NSLOT*48];   // FPS-selected keypoints
__device__ float g_cage[NB*1536];   // cage = grid + disp, [b][512][3]
__device__ float g_pmm[NB*6];       // per-batch min3,max3 of source points

// ----------------------------------------------------------------------------
// Prep: fold BN into weights (transposed layout), zero latents
// ----------------------------------------------------------------------------
__global__ void prep_kernel(
    const float* w1, const float* b1, const float* g1, const float* be1,
    const float* m1, const float* v1,
    const float* w2, const float* b2, const float* g2, const float* be2,
    const float* m2, const float* v2,
    const float* w3, const float* b3, const float* g3, const float* be3,
    const float* m3, const float* v3)
{
    int t = threadIdx.x;
    for (int d = t; d < 64; d += 256) {
        float s = g1[d] * rsqrtf(v1[d] + BN_EPS);
        g_w1f[d*3+0] = w1[d*3+0]*s;
        g_w1f[d*3+1] = w1[d*3+1]*s;
        g_w1f[d*3+2] = w1[d*3+2]*s;
        g_b1f[d] = (b1[d]-m1[d])*s + be1[d];
    }
    for (int d = t; d < 128; d += 256) {
        float s2 = g2[d] * rsqrtf(v2[d] + BN_EPS);
        for (int k = 0; k < 64; k++)  g_w2t[k*128+d] = w2[d*64+k]*s2;
        g_b2f[d] = (b2[d]-m2[d])*s2 + be2[d];
        float s3 = g3[d] * rsqrtf(v3[d] + BN_EPS);
        for (int k = 0; k < 128; k++) g_w3t[k*128+d] = w3[d*128+k]*s3;
        g_b3f[d] = (b3[d]-m3[d])*s3 + be3[d];
    }
    for (int i = t; i < NSLOT*128; i += 256) g_lat[i] = 0;   // 0 bits == 0.0f
}

// ----------------------------------------------------------------------------
// Encoder: 3->64->128->128 MLP + segmented max over N.
// Block: 256 threads, 4 sub-tiles of 64 points.
// Thread (warp=pg, lane=dg) owns 8 points x 4 output dims (32 FFMA accums).
// Weights resident in SMEM; activations staged in SMEM.
// ----------------------------------------------------------------------------
#define ENC_TP   64
#define ENC_SUBT 4
#define ENC_SMEM_FLOATS (64*128 + 128*128 + 64*64 + 64*128 + 64*3 + 8*128)
#define ENC_SMEM_BYTES  (ENC_SMEM_FLOATS*4)

extern __shared__ float enc_smem[];

__global__ __launch_bounds__(256, 1)
void enc_kernel(const float* __restrict__ src, const float* __restrict__ tgt)
{
    float* sW2t = enc_smem;                 // 64*128
    float* sW3t = sW2t + 64*128;            // 128*128
    float* sH1  = sW3t + 128*128;           // 64*64
    float* sH2  = sH1  + 64*64;             // 64*128
    float* sX   = sH2  + 64*128;            // 64*3
    float* sMax = sX   + 64*3;              // 8*128

    const int t    = threadIdx.x;
    const int warp = t >> 5;
    const int lane = t & 31;
    const int pbase = warp * 8;
    const int dbase = lane * 4;
    const int slot = blockIdx.y;

    const float* pts = (slot < 16) ? (src + (size_t)slot*NPTS*3)
                                   : (tgt + (size_t)(slot-16)*NPTS*3);

    for (int i = t; i < 64*128;  i += 256) sW2t[i] = g_w2t[i];
    for (int i = t; i < 128*128; i += 256) sW3t[i] = g_w3t[i];

    for (int st = 0; st < ENC_SUBT; st++) {
        const int p0 = (blockIdx.x * ENC_SUBT + st) * ENC_TP;
        __syncthreads();   // weights ready (st=0); prior readers of sX/sH done
        for (int i = t; i < ENC_TP*3; i += 256) sX[i] = pts[(size_t)p0*3 + i];
        __syncthreads();

        // Layer 1: 64 pts x 64 dims, dot-3
        for (int i = t; i < ENC_TP*64; i += 256) {
            int p = i >> 6, d = i & 63;
            float v = g_b1f[d]
                    + sX[p*3+0]*g_w1f[d*3+0]
                    + sX[p*3+1]*g_w1f[d*3+1]
                    + sX[p*3+2]*g_w1f[d*3+2];
            sH1[p*64+d] = fmaxf(v, 0.f);
        }
        __syncthreads();

        // Layer 2: out 128 dims, K=64
        {
            float acc[8][4];
            #pragma unroll
            for (int j = 0; j < 8; j++) {
                acc[j][0]=0.f; acc[j][1]=0.f; acc[j][2]=0.f; acc[j][3]=0.f;
            }
            #pragma unroll 4
            for (int k = 0; k < 64; k++) {
                float4 w = *(const float4*)(sW2t + k*128 + dbase);
                #pragma unroll
                for (int j = 0; j < 8; j++) {
                    float h = sH1[(pbase+j)*64 + k];
                    acc[j][0] = fmaf(h, w.x, acc[j][0]);
                    acc[j][1] = fmaf(h, w.y, acc[j][1]);
                    acc[j][2] = fmaf(h, w.z, acc[j][2]);
                    acc[j][3] = fmaf(h, w.w, acc[j][3]);
                }
            }
            float4 bb = *(const float4*)(g_b2f + dbase);
            #pragma unroll
            for (int j = 0; j < 8; j++) {
                float4 o;
                o.x = fmaxf(acc[j][0]+bb.x, 0.f);
                o.y = fmaxf(acc[j][1]+bb.y, 0.f);
                o.z = fmaxf(acc[j][2]+bb.z, 0.f);
                o.w = fmaxf(acc[j][3]+bb.w, 0.f);
                *(float4*)(sH2 + (pbase+j)*128 + dbase) = o;
            }
        }
        __syncthreads();

        // Layer 3: out 128 dims, K=128, fused max over the 8 points
        {
            float acc[8][4];
            #pragma unroll
            for (int j = 0; j < 8; j++) {
                acc[j][0]=0.f; acc[j][1]=0.f; acc[j][2]=0.f; acc[j][3]=0.f;
            }
            #pragma unroll 4
            for (int k = 0; k < 128; k++) {
                float4 w = *(const float4*)(sW3t + k*128 + dbase);
                #pragma unroll
                for (int j = 0; j < 8; j++) {
                    float h = sH2[(pbase+j)*128 + k];
                    acc[j][0] = fmaf(h, w.x, acc[j][0]);
                    acc[j][1] = fmaf(h, w.y, acc[j][1]);
                    acc[j][2] = fmaf(h, w.z, acc[j][2]);
                    acc[j][3] = fmaf(h, w.w, acc[j][3]);
                }
            }
            float4 bb = *(const float4*)(g_b3f + dbase);
            float m0=-1e30f, m1=-1e30f, m2=-1e30f, m3=-1e30f;
            #pragma unroll
            for (int j = 0; j < 8; j++) {
                m0 = fmaxf(m0, acc[j][0]+bb.x);
                m1 = fmaxf(m1, acc[j][1]+bb.y);
                m2 = fmaxf(m2, acc[j][2]+bb.z);
                m3 = fmaxf(m3, acc[j][3]+bb.w);
            }
            // relu(max) == max(relu) (monotone)
            sMax[warp*128 + dbase + 0] = fmaxf(m0, 0.f);
            sMax[warp*128 + dbase + 1] = fmaxf(m1, 0.f);
            sMax[warp*128 + dbase + 2] = fmaxf(m2, 0.f);
            sMax[warp*128 + dbase + 3] = fmaxf(m3, 0.f);
        }
        __syncthreads();
        if (t < 128) {
            float v = sMax[t];
            #pragma unroll
            for (int w = 1; w < 8; w++) v = fmaxf(v, sMax[w*128 + t]);
            atomicMax(&g_lat[slot*128 + t], __float_as_int(v)); // v >= 0
        }
    }
}

// ----------------------------------------------------------------------------
// Keypoint MLP: lat[128] -> relu(128) -> 48
// ----------------------------------------------------------------------------
__global__ void kp_kernel(const float* __restrict__ kpw1, const float* __restrict__ kpb1,
                          const float* __restrict__ kpw2, const float* __restrict__ kpb2)
{
    __shared__ float latS[128];
    __shared__ float h[128];
    int slot = blockIdx.x, t = threadIdx.x;
    latS[t] = __int_as_float(g_lat[slot*128 + t]);
    __syncthreads();
    float a = kpb1[t];
    for (int k = 0; k < 128; k++) a = fmaf(latS[k], kpw1[t*128+k], a);
    h[t] = fmaxf(a, 0.f);
    __syncthreads();
    if (t < 48) {
        float o = kpb2[t];
        for (int k = 0; k < 128; k++) o = fmaf(h[k], kpw2[t*128+k], o);
        g_kp[slot*48 + t] = o;
    }
}

// ----------------------------------------------------------------------------
// FPS: per cloud, 16 iterative argmax selections (first = vs MLP keypoints)
// jnp.argmax first-occurrence tie-break preserved (prefer smaller index).
// ----------------------------------------------------------------------------
__global__ __launch_bounds__(1024)
void fps_kernel(const float* __restrict__ src, const float* __restrict__ tgt,
                float* __restrict__ out)
{
    const int slot = blockIdx.x, t = threadIdx.x;
    const float* pts = (slot < 16) ? (src + (size_t)slot*NPTS*3)
                                   : (tgt + (size_t)(slot-16)*NPTS*3);
    float* kout = (slot < 16) ? (out + OUT_DEF + slot*48)
                              : (out + OUT_DEF + OUT_KP + (slot-16)*48);

    __shared__ float skp[48];
    __shared__ float sredV[32];
    __shared__ int   sredI[32];
    __shared__ float selS[3];
    if (t < 48) skp[t] = g_kp[slot*48 + t];

    float px[16], py[16], pz[16], mind[16];
    #pragma unroll
    for (int i = 0; i < 16; i++) {
        int n = t + i*1024;
        px[i] = pts[n*3+0]; py[i] = pts[n*3+1]; pz[i] = pts[n*3+2];
    }
    __syncthreads();

    // d0 = min over 16 MLP keypoints
    #pragma unroll
    for (int i = 0; i < 16; i++) {
        float best = 1e30f;
        #pragma unroll
        for (int k = 0; k < 16; k++) {
            float dx = px[i]-skp[k*3+0], dy = py[i]-skp[k*3+1], dz = pz[i]-skp[k*3+2];
            best = fminf(best, dx*dx + dy*dy + dz*dz);
        }
        mind[i] = best;
    }

    for (int it = 0; it < 16; it++) {
        float bv = -1e30f; int bi = 0x7fffffff;
        #pragma unroll
        for (int i = 0; i < 16; i++) {
            if (mind[i] > bv) { bv = mind[i]; bi = t + i*1024; }  // ascending idx
        }
        #pragma unroll
        for (int o = 16; o > 0; o >>= 1) {
            float ov = __shfl_down_sync(0xffffffffu, bv, o);
            int   oi = __shfl_down_sync(0xffffffffu, bi, o);
            if (ov > bv || (ov == bv && oi < bi)) { bv = ov; bi = oi; }
        }
        if ((t & 31) == 0) { sredV[t>>5] = bv; sredI[t>>5] = bi; }
        __syncthreads();
        if (t < 32) {
            bv = sredV[t]; bi = sredI[t];
            #pragma unroll
            for (int o = 16; o > 0; o >>= 1) {
                float ov = __shfl_down_sync(0xffffffffu, bv, o);
                int   oi = __shfl_down_sync(0xffffffffu, bi, o);
                if (ov > bv || (ov == bv && oi < bi)) { bv = ov; bi = oi; }
            }
            if (t == 0) {
                float sx = pts[bi*3+0], sy = pts[bi*3+1], sz = pts[bi*3+2];
                selS[0] = sx; selS[1] = sy; selS[2] = sz;
                kout[it*3+0] = sx; kout[it*3+1] = sy; kout[it*3+2] = sz;
                g_sel[slot*48 + it*3+0] = sx;
                g_sel[slot*48 + it*3+1] = sy;
                g_sel[slot*48 + it*3+2] = sz;
            }
        }
        __syncthreads();
        float sx = selS[0], sy = selS[1], sz = selS[2];
        #pragma unroll
        for (int i = 0; i < 16; i++) {
            float dx = px[i]-sx, dy = py[i]-sy, dz = pz[i]-sz;
            float d = dx*dx + dy*dy + dz*dz;
            mind[i] = (it == 0) ? d : fminf(mind[i], d);  // it==0: REPLACE (ref)
        }
    }
}

// ----------------------------------------------------------------------------
// Cage MLP: diff[48] -> relu(128) -> 1536; build cage = grid + disp
// ----------------------------------------------------------------------------
__global__ void cage_kernel(const float* __restrict__ cgw1, const float* __restrict__ cgb1,
                            const float* __restrict__ cgw2, const float* __restrict__ cgb2)
{
    __shared__ float diff[48];
    __shared__ float h[128];
    int b = blockIdx.x, t = threadIdx.x;
    if (t < 48) diff[t] = g_sel[(16+b)*48 + t] - g_sel[b*48 + t];
    __syncthreads();
    float a = cgb1[t];
    for (int k = 0; k < 48; k++) a = fmaf(diff[k], cgw1[t*48+k], a);
    h[t] = fmaxf(a, 0.f);
    __syncthreads();
    for (int o = t; o < 1536; o += 128) {
        float acc = cgb2[o];
        for (int k = 0; k < 128; k++) acc = fmaf(h[k], cgw2[o*128+k], acc);
        int c = o % 3, cell = o / 3;
        int i = cell >> 6, j = (cell >> 3) & 7, kz = cell & 7;
        int li = (c == 0) ? i : (c == 1) ? j : kz;
        g_cage[b*1536 + o] = (float)li * (1.0f/7.0f) + acc;
    }
}

// ----------------------------------------------------------------------------
// Per-batch min/max of source points
// ----------------------------------------------------------------------------
__global__ __launch_bounds__(1024)
void pmm_kernel(const float* __restrict__ src)
{
    int b = blockIdx.x, t = threadIdx.x;
    const float* p = src + (size_t)b*NPTS*3;
    float mn0=1e30f, mn1=1e30f, mn2=1e30f, mx0=-1e30f, mx1=-1e30f, mx2=-1e30f;
    for (int n = t; n < NPTS; n += 1024) {
        float x = p[n*3+0], y = p[n*3+1], z = p[n*3+2];
        mn0 = fminf(mn0,x); mx0 = fmaxf(mx0,x);
        mn1 = fminf(mn1,y); mx1 = fmaxf(mx1,y);
        mn2 = fminf(mn2,z); mx2 = fmaxf(mx2,z);
    }
    #pragma unroll
    for (int o = 16; o > 0; o >>= 1) {
        mn0 = fminf(mn0, __shfl_down_sync(0xffffffffu, mn0, o));
        mn1 = fminf(mn1, __shfl_down_sync(0xffffffffu, mn1, o));
        mn2 = fminf(mn2, __shfl_down_sync(0xffffffffu, mn2, o));
        mx0 = fmaxf(mx0, __shfl_down_sync(0xffffffffu, mx0, o));
        mx1 = fmaxf(mx1, __shfl_down_sync(0xffffffffu, mx1, o));
        mx2 = fmaxf(mx2, __shfl_down_sync(0xffffffffu, mx2, o));
    }
    __shared__ float s[32][6];
    if ((t & 31) == 0) {
        s[t>>5][0]=mn0; s[t>>5][1]=mn1; s[t>>5][2]=mn2;
        s[t>>5][3]=mx0; s[t>>5][4]=mx1; s[t>>5][5]=mx2;
    }
    __syncthreads();
    if (t < 32) {
        mn0=s[t][0]; mn1=s[t][1]; mn2=s[t][2]; mx0=s[t][3]; mx1=s[t][4]; mx2=s[t][5];
        #pragma unroll
        for (int o = 16; o > 0; o >>= 1) {
            mn0 = fminf(mn0, __shfl_down_sync(0xffffffffu, mn0, o));
            mn1 = fminf(mn1, __shfl_down_sync(0xffffffffu, mn1, o));
            mn2 = fminf(mn2, __shfl_down_sync(0xffffffffu, mn2, o));
            mx0 = fmaxf(mx0, __shfl_down_sync(0xffffffffu, mx0, o));
            mx1 = fmaxf(mx1, __shfl_down_sync(0xffffffffu, mx1, o));
            mx2 = fmaxf(mx2, __shfl_down_sync(0xffffffffu, mx2, o));
        }
        if (t == 0) {
            g_pmm[b*6+0]=mn0; g_pmm[b*6+1]=mn1; g_pmm[b*6+2]=mn2;
            g_pmm[b*6+3]=mx0; g_pmm[b*6+4]=mx1; g_pmm[b*6+5]=mx2;
        }
    }
}

// ----------------------------------------------------------------------------
// Trilinear cage deform
// ----------------------------------------------------------------------------
__global__ void deform_kernel(const float* __restrict__ src, float* __restrict__ out)
{
    int b = blockIdx.y, t = threadIdx.x;
    __shared__ float cg[1536];
    __shared__ float pm[6];
    for (int i = t; i < 1536; i += 256) cg[i] = g_cage[b*1536 + i];
    if (t < 6) pm[t] = g_pmm[b*6 + t];
    __syncthreads();

    int n = blockIdx.x*256 + t;
    const float* p = src + ((size_t)b*NPTS + n)*3;
    float x = p[0], y = p[1], z = p[2];
    float tx = (x - pm[0]) / (pm[3]-pm[0] + 1e-6f) * 7.f;
    float ty = (y - pm[1]) / (pm[4]-pm[1] + 1e-6f) * 7.f;
    float tz = (z - pm[2]) / (pm[5]-pm[2] + 1e-6f) * 7.f;
    int u = min(max((int)tx, 0), 6);
    int v = min(max((int)ty, 0), 6);
    int w = min(max((int)tz, 0), 6);
    float wx = tx - (float)u, wy = ty - (float)v, wz = tz - (float)w;
    float ax = 1.f-wx, ay = 1.f-wy, az = 1.f-wz;

    int base = u*64 + v*8 + w;
    const float* c000 = &cg[(base     )*3];
    const float* c100 = &cg[(base + 64)*3];
    const float* c010 = &cg[(base +  8)*3];
    const float* c110 = &cg[(base + 72)*3];
    const float* c001 = &cg[(base +  1)*3];
    const float* c101 = &cg[(base + 65)*3];
    const float* c011 = &cg[(base +  9)*3];
    const float* c111 = &cg[(base + 73)*3];

    float w000 = ax*ay*az, w100 = wx*ay*az, w010 = ax*wy*az, w110 = wx*wy*az;
    float w001 = ax*ay*wz, w101 = wx*ay*wz, w011 = ax*wy*wz, w111 = wx*wy*wz;

    #pragma unroll
    for (int c = 0; c < 3; c++) {
        float d = w000*c000[c] + w100*c100[c] + w010*c010[c] + w110*c110[c]
                + w001*c001[c] + w101*c101[c] + w011*c011[c] + w111*c111[c];
        out[((size_t)b*NPTS + n)*3 + c] = p[c] + d;
    }
}

// ----------------------------------------------------------------------------
// Launch
// ----------------------------------------------------------------------------
extern "C" void kernel_launch(void* const* d_in, const int* in_sizes, int n_in,
                              void* d_out, int out_size)
{
    const float* src  = (const float*)d_in[0];
    const float* tgt  = (const float*)d_in[1];
    const float* ew1  = (const float*)d_in[2];
    const float* eb1  = (const float*)d_in[3];
    const float* g1   = (const float*)d_in[4];
    const float* be1  = (const float*)d_in[5];
    const float* m1   = (const float*)d_in[6];
    const float* v1   = (const float*)d_in[7];
    const float* ew2  = (const float*)d_in[8];
    const float* eb2  = (const float*)d_in[9];
    const float* g2   = (const float*)d_in[10];
    const float* be2  = (const float*)d_in[11];
    const float* m2   = (const float*)d_in[12];
    const float* v2   = (const float*)d_in[13];
    const float* ew3  = (const float*)d_in[14];
    const float* eb3  = (const float*)d_in[15];
    const float* g3   = (const float*)d_in[16];
    const float* be3  = (const float*)d_in[17];
    const float* m3   = (const float*)d_in[18];
    const float* v3   = (const float*)d_in[19];
    const float* kpw1 = (const float*)d_in[20];
    const float* kpb1 = (const float*)d_in[21];
    const float* kpw2 = (const float*)d_in[22];
    const float* kpb2 = (const float*)d_in[23];
    const float* cgw1 = (const float*)d_in[24];
    const float* cgb1 = (const float*)d_in[25];
    const float* cgw2 = (const float*)d_in[26];
    const float* cgb2 = (const float*)d_in[27];
    float* out = (float*)d_out;

    cudaFuncSetAttribute(enc_kernel, cudaFuncAttributeMaxDynamicSharedMemorySize,
                         ENC_SMEM_BYTES);

    prep_kernel<<<1, 256>>>(ew1, eb1, g1, be1, m1, v1,
                            ew2, eb2, g2, be2, m2, v2,
                            ew3, eb3, g3, be3, m3, v3);
    enc_kernel<<<dim3(NPTS/(ENC_TP*ENC_SUBT), NSLOT), 256, ENC_SMEM_BYTES>>>(src, tgt);
    kp_kernel<<<NSLOT, 128>>>(kpw1, kpb1, kpw2, kpb2);
    fps_kernel<<<NSLOT, 1024>>>(src, tgt, out);
    cage_kernel<<<NB, 128>>>(cgw1, cgb1, cgw2, cgb2);
    pmm_kernel<<<NB, 1024>>>(src);
    deform_kernel<<<dim3(NPTS/256, NB), 256>>>(src, out);
}